// round 6
// baseline (speedup 1.0000x reference)
#include <cuda_runtime.h>
#include <cstdint>
#include <math.h>

// Problem constants
#define BDIM   4
#define TDIM   4096
#define DDIM   2048
#define DBDIM  512
#define BT     (BDIM * TDIM)   // 16384 tokens
#define EPSV   1e-6f

// ---------------- scratch (static device globals; no runtime allocation) ----
__device__ float g_xc  [(size_t)BT * DDIM];        // tf32-rounded x
__device__ float g_winc[(size_t)DBDIM * DDIM];     // tf32-rounded W_in
__device__ float g_wkc [(size_t)DDIM * DBDIM];     // tf32-rounded W_k
__device__ float g_wvc [(size_t)DDIM * DBDIM];     // tf32-rounded W_v
__device__ float g_z   [(size_t)BT * DBDIM];       // bottleneck proj (rounded)
__device__ float g_zm  [(size_t)BT * 3 * DBDIM];   // z @ [M0|M1|M2]
__device__ float g_y   [(size_t)BT * DBDIM];       // mixed (rounded)
__device__ float g_k   [(size_t)BT * DDIM];        // key proj
__device__ float g_v   [(size_t)BT * DDIM];        // value proj
__device__ float g_wc  [(size_t)3 * DBDIM * DBDIM];// combined mix W [1536,512] (rounded)

// ---------------------------------------------------------------------------
// helpers
// ---------------------------------------------------------------------------
__device__ __forceinline__ float tf32r(float x) {
    uint32_t r;                                    // tf32 dest must be .b32
    asm("cvt.rna.tf32.f32 %0, %1;" : "=r"(r) : "f"(x));
    return __uint_as_float(r);
}

__device__ __forceinline__ uint32_t s2u(const void* p) {
    uint32_t a;
    asm("{ .reg .u64 t; cvta.to.shared.u64 t, %1; cvt.u32.u64 %0, t; }"
        : "=r"(a) : "l"(p));
    return a;
}

__device__ __forceinline__ void cp16(uint32_t dst, const void* src) {
    asm volatile("cp.async.cg.shared.global [%0], [%1], 16;" :: "r"(dst), "l"(src));
}
__device__ __forceinline__ void cp_commit() {
    asm volatile("cp.async.commit_group;" ::: "memory");
}
template<int N> __device__ __forceinline__ void cp_wait() {
    asm volatile("cp.async.wait_group %0;" :: "n"(N) : "memory");
}

__device__ __forceinline__ uint32_t lds_u32(uint32_t addr) {
    uint32_t v;
    asm volatile("ld.shared.b32 %0, [%1];" : "=r"(v) : "r"(addr));
    return v;
}

// mma.sync m16n8k8 tf32 (legacy tensor path, valid on compute_100)
__device__ __forceinline__ void mma_tf32(float& c0, float& c1, float& c2, float& c3,
                                         uint32_t a0, uint32_t a1, uint32_t a2,
                                         uint32_t a3, uint32_t b0, uint32_t b1) {
    asm volatile(
        "mma.sync.aligned.m16n8k8.row.col.f32.tf32.tf32.f32 "
        "{%0,%1,%2,%3}, {%4,%5,%6,%7}, {%8,%9}, {%0,%1,%2,%3};"
        : "+f"(c0), "+f"(c1), "+f"(c2), "+f"(c3)
        : "r"(a0), "r"(a1), "r"(a2), "r"(a3), "r"(b0), "r"(b1));
}

// ---------------------------------------------------------------------------
// TF32 tensor-core NT GEMM: C[M,N] = A[M,K] * W[N,K]^T, fp32 accumulate.
// Operands pre-rounded to tf32. 256x128x32 block tile, 8 warps (4m x 2n),
// warp tile 64x64 (32 HMMA : 32 LDS per k8), 3-stage cp.async.
// SMEM rows padded to 36 floats -> conflict-free fragment loads.
// blockIdx.z selects (W0,C0)/(W1,C1) to fuse the k/v projections.
// ---------------------------------------------------------------------------
#define TBM    256
#define TBN    128
#define TBK    32
#define NSTG   3
#define LROW   36                       // padded row stride (floats)
#define A_STG  (256 * LROW * 4)         // 36864 B
#define B_STG  (128 * LROW * 4)         // 18432 B
#define SOFF_B (NSTG * A_STG)
#define GEMM_SMEM (NSTG * (A_STG + B_STG))   // 165888 B

template<bool RTF32>
__global__ void __launch_bounds__(256)
gemm_tc(const float* __restrict__ A,
        const float* __restrict__ W0, const float* __restrict__ W1,
        float* __restrict__ C0, float* __restrict__ C1,
        int N, int K) {
    extern __shared__ __align__(16) char smem[];
    const uint32_t sb = s2u(smem);

    const float* __restrict__ W = (blockIdx.z == 0) ? W0 : W1;
    float* __restrict__ C = (blockIdx.z == 0) ? C0 : C1;

    const int tid  = threadIdx.x;
    const int lane = tid & 31;
    const int wid  = tid >> 5;
    const int wm   = (wid & 3) * 64;      // warp row offset in tile
    const int wn   = (wid >> 2) * 64;     // warp col offset in tile
    const int g    = lane >> 2;           // groupID 0..7
    const int tg   = lane & 3;            // thread-in-group 0..3

    const int bm = blockIdx.y * TBM;
    const int bn = blockIdx.x * TBN;
    const int num_k = K / TBK;

    const float* Abase = A + (size_t)bm * K;
    const float* Wbase = W + (size_t)bn * K;

    auto load_stage = [&](int ks, int buf) {
        const float* Ap = Abase + ks * TBK;
        const float* Wp = Wbase + ks * TBK;
        uint32_t ab = sb + buf * A_STG;
        uint32_t bb = sb + SOFF_B + buf * B_STG;
        #pragma unroll
        for (int i = 0; i < 8; i++) {             // A: 2048 16B chunks
            int idx = tid + i * 256;
            int r = idx >> 3, c4 = idx & 7;
            cp16(ab + r * (LROW * 4) + c4 * 16, Ap + (size_t)r * K + c4 * 4);
        }
        #pragma unroll
        for (int i = 0; i < 4; i++) {             // B: 1024 16B chunks
            int idx = tid + i * 256;
            int r = idx >> 3, c4 = idx & 7;
            cp16(bb + r * (LROW * 4) + c4 * 16, Wp + (size_t)r * K + c4 * 4);
        }
        cp_commit();
    };

    float acc[4][8][4];
    #pragma unroll
    for (int mi = 0; mi < 4; mi++)
        #pragma unroll
        for (int ni = 0; ni < 8; ni++)
            #pragma unroll
            for (int c = 0; c < 4; c++) acc[mi][ni][c] = 0.f;

    load_stage(0, 0);
    load_stage(1, 1);

    for (int k = 0; k < num_k; k++) {
        cp_wait<NSTG - 2>();
        __syncthreads();                 // stage k ready; stage (k+2)%3 free

        int kn = k + 2;
        if (kn < num_k) load_stage(kn, kn % NSTG); else cp_commit();

        uint32_t ab = sb + (k % NSTG) * A_STG;
        uint32_t bb = sb + SOFF_B + (k % NSTG) * B_STG;

        #pragma unroll
        for (int ks = 0; ks < 4; ks++) {         // 4 x k8 slices
            const int kk = ks * 8;
            uint32_t bf[8][2];
            #pragma unroll
            for (int ni = 0; ni < 8; ni++) {
                int n0 = wn + ni * 8 + g;
                uint32_t base = bb + n0 * (LROW * 4) + (kk + tg) * 4;
                bf[ni][0] = lds_u32(base);
                bf[ni][1] = lds_u32(base + 16);
            }
            #pragma unroll
            for (int mi = 0; mi < 4; mi++) {
                int r0 = wm + mi * 16 + g;
                uint32_t base0 = ab + (r0)     * (LROW * 4) + (kk + tg) * 4;
                uint32_t base1 = ab + (r0 + 8) * (LROW * 4) + (kk + tg) * 4;
                uint32_t a0 = lds_u32(base0);
                uint32_t a1 = lds_u32(base1);
                uint32_t a2 = lds_u32(base0 + 16);
                uint32_t a3 = lds_u32(base1 + 16);
                #pragma unroll
                for (int ni = 0; ni < 8; ni++)
                    mma_tf32(acc[mi][ni][0], acc[mi][ni][1],
                             acc[mi][ni][2], acc[mi][ni][3],
                             a0, a1, a2, a3, bf[ni][0], bf[ni][1]);
            }
        }
    }

    // epilogue: direct float2 stores
    #pragma unroll
    for (int mi = 0; mi < 4; mi++) {
        #pragma unroll
        for (int ni = 0; ni < 8; ni++) {
            int row = bm + wm + mi * 16 + g;
            int col = bn + wn + ni * 8 + tg * 2;
            float v0 = acc[mi][ni][0], v1 = acc[mi][ni][1];
            float v2 = acc[mi][ni][2], v3 = acc[mi][ni][3];
            if (RTF32) { v0 = tf32r(v0); v1 = tf32r(v1);
                         v2 = tf32r(v2); v3 = tf32r(v3); }
            *(float2*)(C + (size_t)row * N + col)       = make_float2(v0, v1);
            *(float2*)(C + (size_t)(row + 8) * N + col) = make_float2(v2, v3);
        }
    }
}

// ---------------------------------------------------------------------------
// tf32 rounding copy
// ---------------------------------------------------------------------------
__global__ void round_copy(const float* __restrict__ src, float* __restrict__ dst,
                           int n4) {
    for (int i = blockIdx.x * blockDim.x + threadIdx.x; i < n4;
         i += gridDim.x * blockDim.x) {
        float4 v = ((const float4*)src)[i];
        v.x = tf32r(v.x); v.y = tf32r(v.y); v.z = tf32r(v.z); v.w = tf32r(v.w);
        ((float4*)dst)[i] = v;
    }
}

// ---------------------------------------------------------------------------
// Combine W_mix[3,512,512] into wc[1536,512] (tf32 rounded):
//   rows [0,512)    = M0 = W2/6 + W3/9 + W4/12   (shifts 0,1)
//   rows [512,1024) = M1 = W3/9 + W4/12          (shift 2)
//   rows [1024,1536)= M2 = W4/12                 (shift 3)
// ---------------------------------------------------------------------------
__global__ void combine_wmix(const float* __restrict__ wmix, float* __restrict__ wc) {
    int idx = blockIdx.x * blockDim.x + threadIdx.x;      // f*512 + e
    if (idx >= DBDIM * DBDIM) return;
    float w2 = wmix[0 * DBDIM * DBDIM + idx];
    float w3 = wmix[1 * DBDIM * DBDIM + idx];
    float w4 = wmix[2 * DBDIM * DBDIM + idx];
    const float c2 = 1.0f / 6.0f, c3 = 1.0f / 9.0f, c4 = 1.0f / 12.0f;
    wc[idx]                     = tf32r(w2 * c2 + w3 * c3 + w4 * c4);
    wc[DBDIM * DBDIM + idx]     = tf32r(w3 * c3 + w4 * c4);
    wc[2 * DBDIM * DBDIM + idx] = tf32r(w4 * c4);
}

// ---------------------------------------------------------------------------
// Gather y[t] = zm0[t] + m1*zm0[t-1] + m2*zm1[t-2] + m3*zm2[t-3] (tf32 round)
// zm row layout: [blk0 | blk1 | blk2], 512 floats each.
// ---------------------------------------------------------------------------
__global__ void __launch_bounds__(128)
build_y(const float* __restrict__ zm, const int* __restrict__ doc,
        float* __restrict__ y) {
    int t  = blockIdx.x;
    int tt = t & (TDIM - 1);
    int d0 = doc[t];
    bool m1 = (tt >= 1) && (doc[t - 1] == d0);
    bool m2 = (tt >= 2) && (doc[t - 2] == d0);
    bool m3 = (tt >= 3) && (doc[t - 3] == d0);

    const float4* p0 = (const float4*)(zm + (size_t)t * 1536);             // blk0
    const float4* p1 = (const float4*)(zm + (size_t)(t - 1) * 1536);       // blk0
    const float4* p2 = (const float4*)(zm + (size_t)(t - 2) * 1536 + 512); // blk1
    const float4* p3 = (const float4*)(zm + (size_t)(t - 3) * 1536 + 1024);// blk2

    int i = threadIdx.x;                 // 128 float4 = 512 floats
    float4 a = p0[i];
    if (m1) { float4 b = p1[i]; a.x += b.x; a.y += b.y; a.z += b.z; a.w += b.w; }
    if (m2) { float4 b = p2[i]; a.x += b.x; a.y += b.y; a.z += b.z; a.w += b.w; }
    if (m3) { float4 b = p3[i]; a.x += b.x; a.y += b.y; a.z += b.z; a.w += b.w; }
    a.x = tf32r(a.x); a.y = tf32r(a.y); a.z = tf32r(a.z); a.w = tf32r(a.w);
    ((float4*)(y + (size_t)t * DBDIM))[i] = a;
}

// ---------------------------------------------------------------------------
// Fused gate + rms(out) + depthwise causal conv(K=4) + SiLU.
// Per token t, recompute scales of tokens t-3..t (per-token, mask-free),
// keep v rows in registers, apply masked taps, SiLU, store final output.
//   scale[ts]: g = Σxk·rsqrt(mean x²+eps)·rsqrt(mean k²+eps)/√D
//              gate = sigmoid(sign(g)√max(|g|,1e-6))
//              scale = gate·rsqrt(gate²·mean v²+eps)
//   out[t,d] = silu(Σ_s mask_s · v[t-s,d]·scale[t-s]·w[d,3-s])
// ---------------------------------------------------------------------------
__global__ void __launch_bounds__(256)
gate_conv(const float* __restrict__ x, const float* __restrict__ k,
          const float* __restrict__ v, const int* __restrict__ doc,
          const float* __restrict__ cw, float* __restrict__ out) {
    int t  = blockIdx.x;
    int tt = t & (TDIM - 1);
    int d0 = doc[t];

    int  trow[4];
    bool msk[4];
    trow[0] = t; msk[0] = true;
    #pragma unroll
    for (int s = 1; s < 4; s++) {
        bool inb = (tt >= s);
        msk[s]  = inb && (doc[t - s] == d0);
        trow[s] = inb ? (t - s) : t;     // clamped row: masked anyway
    }

    float4 va[4][2];
    float sxx[4], sxk[4], skk[4], svv[4];
    #pragma unroll
    for (int s = 0; s < 4; s++) { sxx[s]=0.f; sxk[s]=0.f; skk[s]=0.f; svv[s]=0.f; }

    #pragma unroll
    for (int s = 0; s < 4; s++) {
        const float4* xp = (const float4*)(x + (size_t)trow[s] * DDIM);
        const float4* kp = (const float4*)(k + (size_t)trow[s] * DDIM);
        const float4* vp = (const float4*)(v + (size_t)trow[s] * DDIM);
        #pragma unroll
        for (int r = 0; r < 2; r++) {
            int i = threadIdx.x + r * 256;
            float4 xa = xp[i], ka = kp[i], vv = vp[i];
            va[s][r] = vv;
            sxx[s] += xa.x*xa.x + xa.y*xa.y + xa.z*xa.z + xa.w*xa.w;
            sxk[s] += xa.x*ka.x + xa.y*ka.y + xa.z*ka.z + xa.w*ka.w;
            skk[s] += ka.x*ka.x + ka.y*ka.y + ka.z*ka.z + ka.w*ka.w;
            svv[s] += vv.x*vv.x + vv.y*vv.y + vv.z*vv.z + vv.w*vv.w;
        }
    }

    #pragma unroll
    for (int off = 16; off > 0; off >>= 1) {
        #pragma unroll
        for (int s = 0; s < 4; s++) {
            sxx[s] += __shfl_down_sync(0xffffffffu, sxx[s], off);
            sxk[s] += __shfl_down_sync(0xffffffffu, sxk[s], off);
            skk[s] += __shfl_down_sync(0xffffffffu, skk[s], off);
            svv[s] += __shfl_down_sync(0xffffffffu, svv[s], off);
        }
    }

    __shared__ float sh[16][8];
    __shared__ float s_scale[4];
    int warp = threadIdx.x >> 5, lane = threadIdx.x & 31;
    if (lane == 0) {
        #pragma unroll
        for (int s = 0; s < 4; s++) {
            sh[s * 4 + 0][warp] = sxx[s];
            sh[s * 4 + 1][warp] = sxk[s];
            sh[s * 4 + 2][warp] = skk[s];
            sh[s * 4 + 3][warp] = svv[s];
        }
    }
    __syncthreads();
    if (threadIdx.x < 4) {
        int s = threadIdx.x;
        float a0 = 0.f, a1 = 0.f, a2 = 0.f, a3 = 0.f;
        #pragma unroll
        for (int w = 0; w < 8; w++) {
            a0 += sh[s * 4 + 0][w]; a1 += sh[s * 4 + 1][w];
            a2 += sh[s * 4 + 2][w]; a3 += sh[s * 4 + 3][w];
        }
        const float invD = 1.0f / (float)DDIM;
        float g = a1 * rsqrtf(a0 * invD + EPSV) * rsqrtf(a2 * invD + EPSV)
                     * rsqrtf((float)DDIM);
        float sg = (g > 0.f) ? 1.f : ((g < 0.f) ? -1.f : 0.f);
        float gl = sg * sqrtf(fmaxf(fabsf(g), 1e-6f));
        float gate = 1.0f / (1.0f + expf(-gl));
        float sc = gate * rsqrtf(gate * gate * (a3 * invD) + EPSV);
        s_scale[s] = msk[s] ? sc : 0.f;
    }
    __syncthreads();
    float c0 = s_scale[0], c1 = s_scale[1], c2 = s_scale[2], c3 = s_scale[3];

    #pragma unroll
    for (int r = 0; r < 2; r++) {
        int i = threadIdx.x + r * 256;
        int d = i * 4;
        const float* p0 = (const float*)&va[0][r];
        const float* p1 = (const float*)&va[1][r];
        const float* p2 = (const float*)&va[2][r];
        const float* p3 = (const float*)&va[3][r];
        float4 o;
        float* po = (float*)&o;
        #pragma unroll
        for (int j = 0; j < 4; j++) {
            float4 w = *(const float4*)(cw + (size_t)(d + j) * 4); // taps [0..3]
            float res = p0[j] * c0 * w.w + p1[j] * c1 * w.z
                      + p2[j] * c2 * w.y + p3[j] * c3 * w.x;
            po[j] = res / (1.0f + expf(-res));   // SiLU
        }
        *(float4*)(out + (size_t)t * DDIM + d) = o;
    }
}

// ---------------------------------------------------------------------------
extern "C" void kernel_launch(void* const* d_in, const int* in_sizes, int n_in,
                              void* d_out, int out_size) {
    const float* x      = (const float*)d_in[0];
    const int*   doc    = (const int*)  d_in[1];
    const float* W_in   = (const float*)d_in[2];
    const float* W_mix  = (const float*)d_in[3];
    const float* W_k    = (const float*)d_in[4];
    const float* W_v    = (const float*)d_in[5];
    const float* conv_w = (const float*)d_in[6];
    float* out = (float*)d_out;

    float *xc, *winc, *wkc, *wvc, *z, *zm, *y, *k, *v, *wc;
    cudaGetSymbolAddress((void**)&xc,   g_xc);
    cudaGetSymbolAddress((void**)&winc, g_winc);
    cudaGetSymbolAddress((void**)&wkc,  g_wkc);
    cudaGetSymbolAddress((void**)&wvc,  g_wvc);
    cudaGetSymbolAddress((void**)&z,    g_z);
    cudaGetSymbolAddress((void**)&zm,   g_zm);
    cudaGetSymbolAddress((void**)&y,    g_y);
    cudaGetSymbolAddress((void**)&k,    g_k);
    cudaGetSymbolAddress((void**)&v,    g_v);
    cudaGetSymbolAddress((void**)&wc,   g_wc);

    cudaFuncSetAttribute(gemm_tc<true>,
                         cudaFuncAttributeMaxDynamicSharedMemorySize, GEMM_SMEM);
    cudaFuncSetAttribute(gemm_tc<false>,
                         cudaFuncAttributeMaxDynamicSharedMemorySize, GEMM_SMEM);

    // operand rounding (producers; GEMM inner loop stays cvt-free)
    round_copy<<<2048, 256>>>(x,    xc,   BT * DDIM / 4);
    round_copy<<<512,  256>>>(W_in, winc, DBDIM * DDIM / 4);
    round_copy<<<512,  256>>>(W_k,  wkc,  DDIM * DBDIM / 4);
    round_copy<<<512,  256>>>(W_v,  wvc,  DDIM * DBDIM / 4);
    combine_wmix<<<(DBDIM * DBDIM + 255) / 256, 256>>>(W_mix, wc);

    // 1) z = xc @ winc^T : [16384,2048] x [512,2048]^T   (epilogue rounds)
    gemm_tc<true><<<dim3(DBDIM / TBN, BT / TBM, 1), 256, GEMM_SMEM>>>(
        xc, winc, winc, z, z, DBDIM, DDIM);

    // 2) zm = z @ wc^T : [16384,512] x [1536,512]^T
    gemm_tc<false><<<dim3(3 * DBDIM / TBN, BT / TBM, 1), 256, GEMM_SMEM>>>(
        z, wc, wc, zm, zm, 3 * DBDIM, DBDIM);

    // 3) y gather from shifted zm blocks (rounds)
    build_y<<<BT, 128>>>(zm, doc, y);

    // 4) k = y @ wkc^T, v = y @ wvc^T (fused via blockIdx.z)
    gemm_tc<false><<<dim3(DDIM / TBN, BT / TBM, 2), 256, GEMM_SMEM>>>(
        y, wkc, wvc, k, v, DDIM, DBDIM);

    // 5) fused gate + rms + conv + SiLU -> final output
    gate_conv<<<BT, 256>>>(x, k, v, doc, conv_w, out);
}

// round 7
// speedup vs baseline: 1.6591x; 1.6591x over previous
#include <cuda_runtime.h>
#include <cuda_fp16.h>
#include <cstdint>
#include <math.h>

// Problem constants
#define BDIM   4
#define TDIM   4096
#define DDIM   2048
#define DBDIM  512
#define BT     (BDIM * TDIM)   // 16384 tokens
#define EPSV   1e-6f

// ---------------- scratch (static device globals; no runtime allocation) ----
__device__ __half g_xh  [(size_t)BT * DDIM];         // fp16 x
__device__ __half g_winh[(size_t)DBDIM * DDIM];      // fp16 W_in
__device__ __half g_wkh [(size_t)DDIM * DBDIM];      // fp16 W_k
__device__ __half g_wvh [(size_t)DDIM * DBDIM];      // fp16 W_v
__device__ __half g_wch [(size_t)3 * DBDIM * DBDIM]; // fp16 combined mix W [1536,512]
__device__ __half g_zh  [(size_t)BT * DBDIM];        // fp16 bottleneck proj
__device__ float  g_zm  [(size_t)BT * 3 * DBDIM];    // z @ [M0|M1|M2]  (fp32)
__device__ __half g_yh  [(size_t)BT * DBDIM];        // fp16 mixed
__device__ float  g_k   [(size_t)BT * DDIM];         // key proj
__device__ float  g_v   [(size_t)BT * DDIM];         // value proj
__device__ float  g_scale[(size_t)BT];               // per-token gate*rms scale

// ---------------------------------------------------------------------------
// helpers
// ---------------------------------------------------------------------------
__device__ __forceinline__ uint32_t s2u(const void* p) {
    uint32_t a;
    asm("{ .reg .u64 t; cvta.to.shared.u64 t, %1; cvt.u32.u64 %0, t; }"
        : "=r"(a) : "l"(p));
    return a;
}

__device__ __forceinline__ void cp16(uint32_t dst, const void* src) {
    asm volatile("cp.async.cg.shared.global [%0], [%1], 16;" :: "r"(dst), "l"(src));
}
__device__ __forceinline__ void cp_commit() {
    asm volatile("cp.async.commit_group;" ::: "memory");
}
template<int N> __device__ __forceinline__ void cp_wait() {
    asm volatile("cp.async.wait_group %0;" :: "n"(N) : "memory");
}

__device__ __forceinline__ uint32_t lds_u32(uint32_t addr) {
    uint32_t v;
    asm volatile("ld.shared.b32 %0, [%1];" : "=r"(v) : "r"(addr));
    return v;
}

// mma.sync m16n8k16 fp16 inputs, fp32 accumulate (valid on compute_100)
__device__ __forceinline__ void mma_f16(float& c0, float& c1, float& c2, float& c3,
                                        uint32_t a0, uint32_t a1, uint32_t a2,
                                        uint32_t a3, uint32_t b0, uint32_t b1) {
    asm volatile(
        "mma.sync.aligned.m16n8k16.row.col.f32.f16.f16.f32 "
        "{%0,%1,%2,%3}, {%4,%5,%6,%7}, {%8,%9}, {%0,%1,%2,%3};"
        : "+f"(c0), "+f"(c1), "+f"(c2), "+f"(c3)
        : "r"(a0), "r"(a1), "r"(a2), "r"(a3), "r"(b0), "r"(b1));
}

// ---------------------------------------------------------------------------
// FP16 tensor-core NT GEMM: C[M,N] = A[M,K] * W[N,K]^T, fp32 accumulate.
// A, W fp16. 128x128x64 block tile, 8 warps (4m x 2n), warp tile 32x64,
// 3-stage cp.async, 2 CTAs/SM. SMEM rows padded to 144 B (72 halves)
// -> conflict-free 32-bit fragment loads.
// blockIdx.z selects (W0,C0)/(W1,C1) to fuse the k/v projections.
// OUT_HALF selects fp16 vs fp32 C.
// ---------------------------------------------------------------------------
#define TBM    128
#define TBN    128
#define TBK    64                       // fp16 elements per stage
#define NSTG   3
#define LROWB  144                      // padded row stride in bytes (72 halves)
#define STG_B  (128 * LROWB)            // 18432 bytes per operand per stage
#define SOFF_B (NSTG * STG_B)
#define GEMM_SMEM (2 * NSTG * STG_B)    // 110592 bytes

template<bool OUT_HALF>
__global__ void __launch_bounds__(256, 2)
gemm_f16(const __half* __restrict__ A,
         const __half* __restrict__ W0, const __half* __restrict__ W1,
         void* __restrict__ C0v, void* __restrict__ C1v,
         int N, int K) {
    extern __shared__ __align__(16) char smem[];
    const uint32_t sb = s2u(smem);

    const __half* __restrict__ W = (blockIdx.z == 0) ? W0 : W1;
    void* __restrict__ Cv = (blockIdx.z == 0) ? C0v : C1v;

    const int tid  = threadIdx.x;
    const int lane = tid & 31;
    const int wid  = tid >> 5;
    const int wm   = (wid & 3) * 32;      // warp row offset in tile
    const int wn   = (wid >> 2) * 64;     // warp col offset in tile
    const int g    = lane >> 2;           // groupID 0..7
    const int tg   = lane & 3;            // thread-in-group 0..3

    const int bm = blockIdx.y * TBM;
    const int bn = blockIdx.x * TBN;
    const int num_k = K / TBK;

    const __half* Abase = A + (size_t)bm * K;
    const __half* Wbase = W + (size_t)bn * K;

    auto load_stage = [&](int ks, int buf) {
        const __half* Ap = Abase + ks * TBK;
        const __half* Wp = Wbase + ks * TBK;
        uint32_t ab = sb + buf * STG_B;
        uint32_t bb = sb + SOFF_B + buf * STG_B;
        // 64 halves = 128 B per row = 8 x 16B chunks; 128 rows = 1024 chunks
        #pragma unroll
        for (int i = 0; i < 4; i++) {
            int idx = tid + i * 256;
            int r = idx >> 3, c = idx & 7;
            cp16(ab + r * LROWB + c * 16, Ap + (size_t)r * K + c * 8);
        }
        #pragma unroll
        for (int i = 0; i < 4; i++) {
            int idx = tid + i * 256;
            int r = idx >> 3, c = idx & 7;
            cp16(bb + r * LROWB + c * 16, Wp + (size_t)r * K + c * 8);
        }
        cp_commit();
    };

    float acc[2][8][4];
    #pragma unroll
    for (int mi = 0; mi < 2; mi++)
        #pragma unroll
        for (int ni = 0; ni < 8; ni++)
            #pragma unroll
            for (int c = 0; c < 4; c++) acc[mi][ni][c] = 0.f;

    load_stage(0, 0);
    load_stage(1, 1);

    for (int k = 0; k < num_k; k++) {
        cp_wait<NSTG - 2>();
        __syncthreads();                 // stage k ready; stage (k+2)%3 free

        int kn = k + 2;
        if (kn < num_k) load_stage(kn, kn % NSTG); else cp_commit();

        uint32_t ab = sb + (k % NSTG) * STG_B;
        uint32_t bb = sb + SOFF_B + (k % NSTG) * STG_B;

        #pragma unroll
        for (int ks = 0; ks < 4; ks++) {         // 4 x k16 slices
            const int koff = ks * 32 + tg * 4;   // byte offset: (16*ks + 2*tg) halves
            uint32_t af[2][4], bf[8][2];
            #pragma unroll
            for (int mi = 0; mi < 2; mi++) {
                int r0 = wm + mi * 16 + g;
                uint32_t base0 = ab + (r0)     * LROWB + koff;
                uint32_t base1 = ab + (r0 + 8) * LROWB + koff;
                af[mi][0] = lds_u32(base0);
                af[mi][1] = lds_u32(base1);
                af[mi][2] = lds_u32(base0 + 16);
                af[mi][3] = lds_u32(base1 + 16);
            }
            #pragma unroll
            for (int ni = 0; ni < 8; ni++) {
                int n0 = wn + ni * 8 + g;
                uint32_t base = bb + n0 * LROWB + koff;
                bf[ni][0] = lds_u32(base);
                bf[ni][1] = lds_u32(base + 16);
            }
            #pragma unroll
            for (int mi = 0; mi < 2; mi++)
                #pragma unroll
                for (int ni = 0; ni < 8; ni++)
                    mma_f16(acc[mi][ni][0], acc[mi][ni][1],
                            acc[mi][ni][2], acc[mi][ni][3],
                            af[mi][0], af[mi][1], af[mi][2], af[mi][3],
                            bf[ni][0], bf[ni][1]);
        }
    }

    // epilogue
    #pragma unroll
    for (int mi = 0; mi < 2; mi++) {
        #pragma unroll
        for (int ni = 0; ni < 8; ni++) {
            int row = bm + wm + mi * 16 + g;
            int col = bn + wn + ni * 8 + tg * 2;
            if (OUT_HALF) {
                __half* C = (__half*)Cv;
                *(__half2*)(C + (size_t)row * N + col) =
                    __floats2half2_rn(acc[mi][ni][0], acc[mi][ni][1]);
                *(__half2*)(C + (size_t)(row + 8) * N + col) =
                    __floats2half2_rn(acc[mi][ni][2], acc[mi][ni][3]);
            } else {
                float* C = (float*)Cv;
                *(float2*)(C + (size_t)row * N + col) =
                    make_float2(acc[mi][ni][0], acc[mi][ni][1]);
                *(float2*)(C + (size_t)(row + 8) * N + col) =
                    make_float2(acc[mi][ni][2], acc[mi][ni][3]);
            }
        }
    }
}

// ---------------------------------------------------------------------------
// fp32 -> fp16 copy
// ---------------------------------------------------------------------------
__global__ void half_copy(const float* __restrict__ src, __half* __restrict__ dst,
                          int n4) {
    for (int i = blockIdx.x * blockDim.x + threadIdx.x; i < n4;
         i += gridDim.x * blockDim.x) {
        float4 v = ((const float4*)src)[i];
        __half2* d = (__half2*)dst + (size_t)i * 2;
        d[0] = __floats2half2_rn(v.x, v.y);
        d[1] = __floats2half2_rn(v.z, v.w);
    }
}

// ---------------------------------------------------------------------------
// Combine W_mix[3,512,512] into wch[1536,512] fp16:
//   rows [0,512)    = M0 = W2/6 + W3/9 + W4/12   (shifts 0,1)
//   rows [512,1024) = M1 = W3/9 + W4/12          (shift 2)
//   rows [1024,1536)= M2 = W4/12                 (shift 3)
// ---------------------------------------------------------------------------
__global__ void combine_wmix(const float* __restrict__ wmix, __half* __restrict__ wc) {
    int idx = blockIdx.x * blockDim.x + threadIdx.x;      // f*512 + e
    if (idx >= DBDIM * DBDIM) return;
    float w2 = wmix[0 * DBDIM * DBDIM + idx];
    float w3 = wmix[1 * DBDIM * DBDIM + idx];
    float w4 = wmix[2 * DBDIM * DBDIM + idx];
    const float c2 = 1.0f / 6.0f, c3 = 1.0f / 9.0f, c4 = 1.0f / 12.0f;
    wc[idx]                     = __float2half_rn(w2 * c2 + w3 * c3 + w4 * c4);
    wc[DBDIM * DBDIM + idx]     = __float2half_rn(w3 * c3 + w4 * c4);
    wc[2 * DBDIM * DBDIM + idx] = __float2half_rn(w4 * c4);
}

// ---------------------------------------------------------------------------
// Gather y[t] = zm0[t] + m1*zm0[t-1] + m2*zm1[t-2] + m3*zm2[t-3] -> fp16
// zm row layout: [blk0 | blk1 | blk2], 512 floats each.
// ---------------------------------------------------------------------------
__global__ void __launch_bounds__(128)
build_y(const float* __restrict__ zm, const int* __restrict__ doc,
        __half* __restrict__ y) {
    int t  = blockIdx.x;
    int tt = t & (TDIM - 1);
    int d0 = doc[t];
    bool m1 = (tt >= 1) && (doc[t - 1] == d0);
    bool m2 = (tt >= 2) && (doc[t - 2] == d0);
    bool m3 = (tt >= 3) && (doc[t - 3] == d0);

    const float4* p0 = (const float4*)(zm + (size_t)t * 1536);             // blk0
    const float4* p1 = (const float4*)(zm + (size_t)(t - 1) * 1536);       // blk0
    const float4* p2 = (const float4*)(zm + (size_t)(t - 2) * 1536 + 512); // blk1
    const float4* p3 = (const float4*)(zm + (size_t)(t - 3) * 1536 + 1024);// blk2

    int i = threadIdx.x;                 // 128 float4 = 512 floats
    float4 a = p0[i];
    if (m1) { float4 b = p1[i]; a.x += b.x; a.y += b.y; a.z += b.z; a.w += b.w; }
    if (m2) { float4 b = p2[i]; a.x += b.x; a.y += b.y; a.z += b.z; a.w += b.w; }
    if (m3) { float4 b = p3[i]; a.x += b.x; a.y += b.y; a.z += b.z; a.w += b.w; }
    __half2* yp = (__half2*)(y + (size_t)t * DBDIM) + i * 2;
    yp[0] = __floats2half2_rn(a.x, a.y);
    yp[1] = __floats2half2_rn(a.z, a.w);
}

// ---------------------------------------------------------------------------
// Gate scale: per token compute scale[t] = gate * rsqrt(gate^2*mean(v^2)+eps),
// gate = sigmoid(sign(g)*sqrt(max(|g|,1e-6))),
// g = Sxk * rsqrt(mean x^2+eps) * rsqrt(mean k^2+eps) / sqrt(D).
// ---------------------------------------------------------------------------
__global__ void __launch_bounds__(256)
gate_scale(const float* __restrict__ x, const float* __restrict__ k,
           const float* __restrict__ v, float* __restrict__ scale) {
    int t = blockIdx.x;
    const float4* xp = (const float4*)(x + (size_t)t * DDIM);
    const float4* kp = (const float4*)(k + (size_t)t * DDIM);
    const float4* vp = (const float4*)(v + (size_t)t * DDIM);

    float sxx = 0.f, sxk = 0.f, skk = 0.f, svv = 0.f;
    #pragma unroll
    for (int r = 0; r < 2; r++) {
        int i = threadIdx.x + r * 256;
        float4 xa = xp[i], ka = kp[i], va = vp[i];
        sxx += xa.x * xa.x + xa.y * xa.y + xa.z * xa.z + xa.w * xa.w;
        sxk += xa.x * ka.x + xa.y * ka.y + xa.z * ka.z + xa.w * ka.w;
        skk += ka.x * ka.x + ka.y * ka.y + ka.z * ka.z + ka.w * ka.w;
        svv += va.x * va.x + va.y * va.y + va.z * va.z + va.w * va.w;
    }
    #pragma unroll
    for (int off = 16; off > 0; off >>= 1) {
        sxx += __shfl_down_sync(0xffffffffu, sxx, off);
        sxk += __shfl_down_sync(0xffffffffu, sxk, off);
        skk += __shfl_down_sync(0xffffffffu, skk, off);
        svv += __shfl_down_sync(0xffffffffu, svv, off);
    }
    __shared__ float sh[4][8];
    int warp = threadIdx.x >> 5, lane = threadIdx.x & 31;
    if (lane == 0) {
        sh[0][warp] = sxx; sh[1][warp] = sxk; sh[2][warp] = skk; sh[3][warp] = svv;
    }
    __syncthreads();
    if (threadIdx.x == 0) {
        float a0 = 0.f, a1 = 0.f, a2 = 0.f, a3 = 0.f;
        #pragma unroll
        for (int w = 0; w < 8; w++) {
            a0 += sh[0][w]; a1 += sh[1][w]; a2 += sh[2][w]; a3 += sh[3][w];
        }
        const float invD = 1.0f / (float)DDIM;
        float g = a1 * rsqrtf(a0 * invD + EPSV) * rsqrtf(a2 * invD + EPSV)
                     * rsqrtf((float)DDIM);
        float sg = (g > 0.f) ? 1.f : ((g < 0.f) ? -1.f : 0.f);
        float gl = sg * sqrtf(fmaxf(fabsf(g), 1e-6f));
        float gate = 1.0f / (1.0f + expf(-gl));
        scale[t] = gate * rsqrtf(gate * gate * (a3 * invD) + EPSV);
    }
}

// ---------------------------------------------------------------------------
// Depthwise causal conv (K=4) + SiLU, with normed[t] = v[t]*scale[t] formed
// on the fly (v rows t-1..t-3 hit L2 from neighboring blocks).
// out[t,d] = silu( sum_s mask_s * v[t-s,d]*scale[t-s]*cw[d,3-s] )
// ---------------------------------------------------------------------------
__global__ void __launch_bounds__(256)
conv_silu(const float* __restrict__ v, const float* __restrict__ scale,
          const int* __restrict__ doc, const float* __restrict__ cw,
          float* __restrict__ out) {
    int t  = blockIdx.x;
    int tt = t & (TDIM - 1);
    int d0 = doc[t];

    float c0 = scale[t], c1 = 0.f, c2 = 0.f, c3 = 0.f;
    int r1 = t, r2 = t, r3 = t;
    if (tt >= 1 && doc[t - 1] == d0) { c1 = scale[t - 1]; r1 = t - 1; }
    if (tt >= 2 && doc[t - 2] == d0) { c2 = scale[t - 2]; r2 = t - 2; }
    if (tt >= 3 && doc[t - 3] == d0) { c3 = scale[t - 3]; r3 = t - 3; }

    const float* n0 = v + (size_t)t  * DDIM;
    const float* n1 = v + (size_t)r1 * DDIM;
    const float* n2 = v + (size_t)r2 * DDIM;
    const float* n3 = v + (size_t)r3 * DDIM;

    #pragma unroll
    for (int r = 0; r < 2; r++) {
        int d4 = threadIdx.x + r * 256;
        int d  = d4 * 4;
        float4 a0 = *(const float4*)(n0 + d);
        float4 a1 = *(const float4*)(n1 + d);
        float4 a2 = *(const float4*)(n2 + d);
        float4 a3 = *(const float4*)(n3 + d);

        const float* p0 = (const float*)&a0;
        const float* p1 = (const float*)&a1;
        const float* p2 = (const float*)&a2;
        const float* p3 = (const float*)&a3;

        float4 o;
        float* po = (float*)&o;
        #pragma unroll
        for (int i = 0; i < 4; i++) {
            float4 w = *(const float4*)(cw + (size_t)(d + i) * 4); // taps [0..3]
            float res = p0[i] * c0 * w.w + p1[i] * c1 * w.z
                      + p2[i] * c2 * w.y + p3[i] * c3 * w.x;
            po[i] = res / (1.0f + expf(-res));   // SiLU
        }
        *(float4*)(out + (size_t)t * DDIM + d) = o;
    }
}

// ---------------------------------------------------------------------------
extern "C" void kernel_launch(void* const* d_in, const int* in_sizes, int n_in,
                              void* d_out, int out_size) {
    const float* x      = (const float*)d_in[0];
    const int*   doc    = (const int*)  d_in[1];
    const float* W_in   = (const float*)d_in[2];
    const float* W_mix  = (const float*)d_in[3];
    const float* W_k    = (const float*)d_in[4];
    const float* W_v    = (const float*)d_in[5];
    const float* conv_w = (const float*)d_in[6];
    float* out = (float*)d_out;

    __half *xh, *winh, *wkh, *wvh, *wch, *zh, *yh;
    float *zm, *k, *v, *scale;
    cudaGetSymbolAddress((void**)&xh,    g_xh);
    cudaGetSymbolAddress((void**)&winh,  g_winh);
    cudaGetSymbolAddress((void**)&wkh,   g_wkh);
    cudaGetSymbolAddress((void**)&wvh,   g_wvh);
    cudaGetSymbolAddress((void**)&wch,   g_wch);
    cudaGetSymbolAddress((void**)&zh,    g_zh);
    cudaGetSymbolAddress((void**)&zm,    g_zm);
    cudaGetSymbolAddress((void**)&yh,    g_yh);
    cudaGetSymbolAddress((void**)&k,     g_k);
    cudaGetSymbolAddress((void**)&v,     g_v);
    cudaGetSymbolAddress((void**)&scale, g_scale);

    cudaFuncSetAttribute(gemm_f16<true>,
                         cudaFuncAttributeMaxDynamicSharedMemorySize, GEMM_SMEM);
    cudaFuncSetAttribute(gemm_f16<false>,
                         cudaFuncAttributeMaxDynamicSharedMemorySize, GEMM_SMEM);

    // operand conversion to fp16
    half_copy<<<2048, 256>>>(x,    xh,   BT * DDIM / 4);
    half_copy<<<512,  256>>>(W_in, winh, DBDIM * DDIM / 4);
    half_copy<<<512,  256>>>(W_k,  wkh,  DDIM * DBDIM / 4);
    half_copy<<<512,  256>>>(W_v,  wvh,  DDIM * DBDIM / 4);
    combine_wmix<<<(DBDIM * DBDIM + 255) / 256, 256>>>(W_mix, wch);

    // 1) z = xh @ winh^T : [16384,2048] x [512,2048]^T -> fp16
    gemm_f16<true><<<dim3(DBDIM / TBN, BT / TBM, 1), 256, GEMM_SMEM>>>(
        xh, winh, winh, zh, zh, DBDIM, DDIM);

    // 2) zm = zh @ wch^T : [16384,512] x [1536,512]^T -> fp32
    gemm_f16<false><<<dim3(3 * DBDIM / TBN, BT / TBM, 1), 256, GEMM_SMEM>>>(
        zh, wch, wch, zm, zm, 3 * DBDIM, DBDIM);

    // 3) y gather from shifted zm blocks -> fp16
    build_y<<<BT, 128>>>(zm, doc, yh);

    // 4) k = yh @ wkh^T, v = yh @ wvh^T (fused via blockIdx.z) -> fp32
    gemm_f16<false><<<dim3(DDIM / TBN, BT / TBM, 2), 256, GEMM_SMEM>>>(
        yh, wkh, wvh, k, v, DDIM, DBDIM);

    // 5) per-token gate scale
    gate_scale<<<BT, 256>>>(x, k, v, scale);

    // 6) depthwise causal conv + SiLU -> final output
    conv_silu<<<BT, 256>>>(v, scale, doc, conv_w, out);
}

// round 8
// speedup vs baseline: 1.8087x; 1.0902x over previous
#include <cuda_runtime.h>
#include <cuda_fp16.h>
#include <cstdint>
#include <math.h>

// Problem constants
#define BDIM   4
#define TDIM   4096
#define DDIM   2048
#define DBDIM  512
#define BT     (BDIM * TDIM)   // 16384 tokens
#define EPSV   1e-6f

// ---------------- scratch (static device globals; no runtime allocation) ----
__device__ __half g_xh  [(size_t)BT * DDIM];         // fp16 x
__device__ __half g_winh[(size_t)DBDIM * DDIM];      // fp16 W_in
__device__ __half g_wkh [(size_t)DDIM * DBDIM];      // fp16 W_k
__device__ __half g_wvh [(size_t)DDIM * DBDIM];      // fp16 W_v
__device__ __half g_wch [(size_t)3 * DBDIM * DBDIM]; // fp16 combined mix W [1536,512]
__device__ __half g_zh  [(size_t)BT * DBDIM];        // fp16 bottleneck proj
__device__ __half g_zm  [(size_t)BT * 3 * DBDIM];    // fp16 z @ [M0|M1|M2]
__device__ __half g_yh  [(size_t)BT * DBDIM];        // fp16 mixed
__device__ float  g_k   [(size_t)BT * DDIM];         // key proj
__device__ float  g_v   [(size_t)BT * DDIM];         // value proj
__device__ float  g_scale[(size_t)BT];               // per-token gate*rms scale

// ---------------------------------------------------------------------------
// helpers
// ---------------------------------------------------------------------------
__device__ __forceinline__ uint32_t s2u(const void* p) {
    uint32_t a;
    asm("{ .reg .u64 t; cvta.to.shared.u64 t, %1; cvt.u32.u64 %0, t; }"
        : "=r"(a) : "l"(p));
    return a;
}

__device__ __forceinline__ void cp16(uint32_t dst, const void* src) {
    asm volatile("cp.async.cg.shared.global [%0], [%1], 16;" :: "r"(dst), "l"(src));
}
__device__ __forceinline__ void cp_commit() {
    asm volatile("cp.async.commit_group;" ::: "memory");
}
template<int N> __device__ __forceinline__ void cp_wait() {
    asm volatile("cp.async.wait_group %0;" :: "n"(N) : "memory");
}

__device__ __forceinline__ void ldmx4(uint32_t& r0, uint32_t& r1,
                                      uint32_t& r2, uint32_t& r3, uint32_t addr) {
    asm volatile("ldmatrix.sync.aligned.m8n8.x4.shared.b16 {%0,%1,%2,%3}, [%4];"
        : "=r"(r0), "=r"(r1), "=r"(r2), "=r"(r3) : "r"(addr));
}

// mma.sync m16n8k16 fp16 inputs, fp32 accumulate (valid on compute_100)
__device__ __forceinline__ void mma_f16(float& c0, float& c1, float& c2, float& c3,
                                        uint32_t a0, uint32_t a1, uint32_t a2,
                                        uint32_t a3, uint32_t b0, uint32_t b1) {
    asm volatile(
        "mma.sync.aligned.m16n8k16.row.col.f32.f16.f16.f32 "
        "{%0,%1,%2,%3}, {%4,%5,%6,%7}, {%8,%9}, {%0,%1,%2,%3};"
        : "+f"(c0), "+f"(c1), "+f"(c2), "+f"(c3)
        : "r"(a0), "r"(a1), "r"(a2), "r"(a3), "r"(b0), "r"(b1));
}

// ---------------------------------------------------------------------------
// FP16 tensor-core NT GEMM: C[M,N] = A[M,K] * W[N,K]^T, fp32 accumulate.
// 128x128x64 block tile, 8 warps (4m x 2n), warp tile 32x64, 3-stage cp.async,
// 2 CTAs/SM. ldmatrix.x4 fragment loads (6 per k16-slice vs 24 LDS.32).
// SMEM rows padded to 144 B -> conflict-free ldmatrix (banks 4r mod 32).
// blockIdx.z selects (W0,C0)/(W1,C1) to fuse the k/v projections.
// OUT_HALF selects fp16 vs fp32 C.
// ---------------------------------------------------------------------------
#define TBM    128
#define TBN    128
#define TBK    64                       // fp16 elements per stage
#define NSTG   3
#define LROWB  144                      // padded row stride in bytes (72 halves)
#define STG_B  (128 * LROWB)            // 18432 bytes per operand per stage
#define SOFF_B (NSTG * STG_B)
#define GEMM_SMEM (2 * NSTG * STG_B)    // 110592 bytes

template<bool OUT_HALF>
__global__ void __launch_bounds__(256, 2)
gemm_f16(const __half* __restrict__ A,
         const __half* __restrict__ W0, const __half* __restrict__ W1,
         void* __restrict__ C0v, void* __restrict__ C1v,
         int N, int K) {
    extern __shared__ __align__(16) char smem[];
    const uint32_t sb = s2u(smem);

    const __half* __restrict__ W = (blockIdx.z == 0) ? W0 : W1;
    void* __restrict__ Cv = (blockIdx.z == 0) ? C0v : C1v;

    const int tid  = threadIdx.x;
    const int lane = tid & 31;
    const int wid  = tid >> 5;
    const int wm   = (wid & 3) * 32;      // warp row offset in tile
    const int wn   = (wid >> 2) * 64;     // warp col offset in tile
    const int g    = lane >> 2;           // groupID 0..7
    const int tg   = lane & 3;            // thread-in-group 0..3

    // ldmatrix per-lane base offsets (within a stage buffer)
    // A x4: lanes 0-7 -> (row l, k0..7), 8-15 -> (row l+8, k0..7),
    //       16-23 -> (row l, k8..15), 24-31 -> (row l+8, k8..15)
    const uint32_t aoff = (uint32_t)(wm + (lane & 7) + ((lane >> 3) & 1) * 8) * LROWB
                        + ((lane >> 4) & 1) * 16;
    // B x4: lanes 0-7 -> (n l, k0..7), 8-15 -> (n l, k8..15),
    //       16-23 -> (n l+8, k0..7), 24-31 -> (n l+8, k8..15)
    const uint32_t boff = (uint32_t)(wn + (lane & 7) + ((lane >> 4) & 1) * 8) * LROWB
                        + ((lane >> 3) & 1) * 16;

    const int bm = blockIdx.y * TBM;
    const int bn = blockIdx.x * TBN;
    const int num_k = K / TBK;

    const __half* Abase = A + (size_t)bm * K;
    const __half* Wbase = W + (size_t)bn * K;

    auto load_stage = [&](int ks, int buf) {
        const __half* Ap = Abase + ks * TBK;
        const __half* Wp = Wbase + ks * TBK;
        uint32_t ab = sb + buf * STG_B;
        uint32_t bb = sb + SOFF_B + buf * STG_B;
        #pragma unroll
        for (int i = 0; i < 4; i++) {
            int idx = tid + i * 256;
            int r = idx >> 3, c = idx & 7;
            cp16(ab + r * LROWB + c * 16, Ap + (size_t)r * K + c * 8);
        }
        #pragma unroll
        for (int i = 0; i < 4; i++) {
            int idx = tid + i * 256;
            int r = idx >> 3, c = idx & 7;
            cp16(bb + r * LROWB + c * 16, Wp + (size_t)r * K + c * 8);
        }
        cp_commit();
    };

    float acc[2][8][4];
    #pragma unroll
    for (int mi = 0; mi < 2; mi++)
        #pragma unroll
        for (int ni = 0; ni < 8; ni++)
            #pragma unroll
            for (int c = 0; c < 4; c++) acc[mi][ni][c] = 0.f;

    load_stage(0, 0);
    load_stage(1, 1);

    for (int k = 0; k < num_k; k++) {
        cp_wait<NSTG - 2>();
        __syncthreads();                 // stage k ready; stage (k+2)%3 free

        int kn = k + 2;
        if (kn < num_k) load_stage(kn, kn % NSTG); else cp_commit();

        uint32_t ab = sb + (k % NSTG) * STG_B + aoff;
        uint32_t bb = sb + SOFF_B + (k % NSTG) * STG_B + boff;

        #pragma unroll
        for (int ks = 0; ks < 4; ks++) {         // 4 x k16 slices
            const uint32_t koff = ks * 32;       // 16 halves per slice
            uint32_t af[2][4], bf[4][4];
            ldmx4(af[0][0], af[0][1], af[0][2], af[0][3], ab + koff);
            ldmx4(af[1][0], af[1][1], af[1][2], af[1][3],
                  ab + 16 * LROWB + koff);
            #pragma unroll
            for (int nj = 0; nj < 4; nj++)
                ldmx4(bf[nj][0], bf[nj][1], bf[nj][2], bf[nj][3],
                      bb + nj * 16 * LROWB + koff);
            #pragma unroll
            for (int mi = 0; mi < 2; mi++)
                #pragma unroll
                for (int ni = 0; ni < 8; ni++) {
                    const uint32_t b0 = bf[ni >> 1][(ni & 1) * 2];
                    const uint32_t b1 = bf[ni >> 1][(ni & 1) * 2 + 1];
                    mma_f16(acc[mi][ni][0], acc[mi][ni][1],
                            acc[mi][ni][2], acc[mi][ni][3],
                            af[mi][0], af[mi][1], af[mi][2], af[mi][3],
                            b0, b1);
                }
        }
    }

    // epilogue
    #pragma unroll
    for (int mi = 0; mi < 2; mi++) {
        #pragma unroll
        for (int ni = 0; ni < 8; ni++) {
            int row = bm + wm + mi * 16 + g;
            int col = bn + wn + ni * 8 + tg * 2;
            if (OUT_HALF) {
                __half* C = (__half*)Cv;
                *(__half2*)(C + (size_t)row * N + col) =
                    __floats2half2_rn(acc[mi][ni][0], acc[mi][ni][1]);
                *(__half2*)(C + (size_t)(row + 8) * N + col) =
                    __floats2half2_rn(acc[mi][ni][2], acc[mi][ni][3]);
            } else {
                float* C = (float*)Cv;
                *(float2*)(C + (size_t)row * N + col) =
                    make_float2(acc[mi][ni][0], acc[mi][ni][1]);
                *(float2*)(C + (size_t)(row + 8) * N + col) =
                    make_float2(acc[mi][ni][2], acc[mi][ni][3]);
            }
        }
    }
}

// ---------------------------------------------------------------------------
// fp32 -> fp16 copy
// ---------------------------------------------------------------------------
__global__ void half_copy(const float* __restrict__ src, __half* __restrict__ dst,
                          int n4) {
    for (int i = blockIdx.x * blockDim.x + threadIdx.x; i < n4;
         i += gridDim.x * blockDim.x) {
        float4 v = ((const float4*)src)[i];
        __half2* d = (__half2*)dst + (size_t)i * 2;
        d[0] = __floats2half2_rn(v.x, v.y);
        d[1] = __floats2half2_rn(v.z, v.w);
    }
}

// ---------------------------------------------------------------------------
// Combine W_mix[3,512,512] into wch[1536,512] fp16:
//   rows [0,512)    = M0 = W2/6 + W3/9 + W4/12   (shifts 0,1)
//   rows [512,1024) = M1 = W3/9 + W4/12          (shift 2)
//   rows [1024,1536)= M2 = W4/12                 (shift 3)
// ---------------------------------------------------------------------------
__global__ void combine_wmix(const float* __restrict__ wmix, __half* __restrict__ wc) {
    int idx = blockIdx.x * blockDim.x + threadIdx.x;      // f*512 + e
    if (idx >= DBDIM * DBDIM) return;
    float w2 = wmix[0 * DBDIM * DBDIM + idx];
    float w3 = wmix[1 * DBDIM * DBDIM + idx];
    float w4 = wmix[2 * DBDIM * DBDIM + idx];
    const float c2 = 1.0f / 6.0f, c3 = 1.0f / 9.0f, c4 = 1.0f / 12.0f;
    wc[idx]                     = __float2half_rn(w2 * c2 + w3 * c3 + w4 * c4);
    wc[DBDIM * DBDIM + idx]     = __float2half_rn(w3 * c3 + w4 * c4);
    wc[2 * DBDIM * DBDIM + idx] = __float2half_rn(w4 * c4);
}

// ---------------------------------------------------------------------------
// Gather y[t] = zm0[t] + m1*zm0[t-1] + m2*zm1[t-2] + m3*zm2[t-3]
// zm fp16, row layout [blk0 | blk1 | blk2], 512 halves each. Output fp16.
// ---------------------------------------------------------------------------
__global__ void __launch_bounds__(128)
build_y(const __half* __restrict__ zm, const int* __restrict__ doc,
        __half* __restrict__ y) {
    int t  = blockIdx.x;
    int tt = t & (TDIM - 1);
    int d0 = doc[t];
    bool m1 = (tt >= 1) && (doc[t - 1] == d0);
    bool m2 = (tt >= 2) && (doc[t - 2] == d0);
    bool m3 = (tt >= 3) && (doc[t - 3] == d0);

    const float2* p0 = (const float2*)(zm + (size_t)t * 1536);             // blk0
    const float2* p1 = (const float2*)(zm + (size_t)(t - 1) * 1536);       // blk0
    const float2* p2 = (const float2*)(zm + (size_t)(t - 2) * 1536 + 512); // blk1
    const float2* p3 = (const float2*)(zm + (size_t)(t - 3) * 1536 + 1024);// blk2

    int i = threadIdx.x;                 // 128 x 4 halves = 512
    float2 r0 = p0[i];                   // 4 halves as float2 bits
    __half2* h0 = (__half2*)&r0;
    float2 lo = __half22float2(h0[0]);
    float2 hi = __half22float2(h0[1]);
    if (m1) {
        float2 q = p1[i]; __half2* h = (__half2*)&q;
        float2 a = __half22float2(h[0]), b = __half22float2(h[1]);
        lo.x += a.x; lo.y += a.y; hi.x += b.x; hi.y += b.y;
    }
    if (m2) {
        float2 q = p2[i]; __half2* h = (__half2*)&q;
        float2 a = __half22float2(h[0]), b = __half22float2(h[1]);
        lo.x += a.x; lo.y += a.y; hi.x += b.x; hi.y += b.y;
    }
    if (m3) {
        float2 q = p3[i]; __half2* h = (__half2*)&q;
        float2 a = __half22float2(h[0]), b = __half22float2(h[1]);
        lo.x += a.x; lo.y += a.y; hi.x += b.x; hi.y += b.y;
    }
    __half2* yp = (__half2*)(y + (size_t)t * DBDIM) + i * 2;
    yp[0] = __floats2half2_rn(lo.x, lo.y);
    yp[1] = __floats2half2_rn(hi.x, hi.y);
}

// ---------------------------------------------------------------------------
// Gate scale: per token compute scale[t] = gate * rsqrt(gate^2*mean(v^2)+eps)
// ---------------------------------------------------------------------------
__global__ void __launch_bounds__(256)
gate_scale(const float* __restrict__ x, const float* __restrict__ k,
           const float* __restrict__ v, float* __restrict__ scale) {
    int t = blockIdx.x;
    const float4* xp = (const float4*)(x + (size_t)t * DDIM);
    const float4* kp = (const float4*)(k + (size_t)t * DDIM);
    const float4* vp = (const float4*)(v + (size_t)t * DDIM);

    float sxx = 0.f, sxk = 0.f, skk = 0.f, svv = 0.f;
    #pragma unroll
    for (int r = 0; r < 2; r++) {
        int i = threadIdx.x + r * 256;
        float4 xa = xp[i], ka = kp[i], va = vp[i];
        sxx += xa.x * xa.x + xa.y * xa.y + xa.z * xa.z + xa.w * xa.w;
        sxk += xa.x * ka.x + xa.y * ka.y + xa.z * ka.z + xa.w * ka.w;
        skk += ka.x * ka.x + ka.y * ka.y + ka.z * ka.z + ka.w * ka.w;
        svv += va.x * va.x + va.y * va.y + va.z * va.z + va.w * va.w;
    }
    #pragma unroll
    for (int off = 16; off > 0; off >>= 1) {
        sxx += __shfl_down_sync(0xffffffffu, sxx, off);
        sxk += __shfl_down_sync(0xffffffffu, sxk, off);
        skk += __shfl_down_sync(0xffffffffu, skk, off);
        svv += __shfl_down_sync(0xffffffffu, svv, off);
    }
    __shared__ float sh[4][8];
    int warp = threadIdx.x >> 5, lane = threadIdx.x & 31;
    if (lane == 0) {
        sh[0][warp] = sxx; sh[1][warp] = sxk; sh[2][warp] = skk; sh[3][warp] = svv;
    }
    __syncthreads();
    if (threadIdx.x == 0) {
        float a0 = 0.f, a1 = 0.f, a2 = 0.f, a3 = 0.f;
        #pragma unroll
        for (int w = 0; w < 8; w++) {
            a0 += sh[0][w]; a1 += sh[1][w]; a2 += sh[2][w]; a3 += sh[3][w];
        }
        const float invD = 1.0f / (float)DDIM;
        float g = a1 * rsqrtf(a0 * invD + EPSV) * rsqrtf(a2 * invD + EPSV)
                     * rsqrtf((float)DDIM);
        float sg = (g > 0.f) ? 1.f : ((g < 0.f) ? -1.f : 0.f);
        float gl = sg * sqrtf(fmaxf(fabsf(g), 1e-6f));
        float gate = 1.0f / (1.0f + expf(-gl));
        scale[t] = gate * rsqrtf(gate * gate * (a3 * invD) + EPSV);
    }
}

// ---------------------------------------------------------------------------
// Depthwise causal conv (K=4) + SiLU; normed[t] = v[t]*scale[t] on the fly.
// ---------------------------------------------------------------------------
__global__ void __launch_bounds__(256)
conv_silu(const float* __restrict__ v, const float* __restrict__ scale,
          const int* __restrict__ doc, const float* __restrict__ cw,
          float* __restrict__ out) {
    int t  = blockIdx.x;
    int tt = t & (TDIM - 1);
    int d0 = doc[t];

    float c0 = scale[t], c1 = 0.f, c2 = 0.f, c3 = 0.f;
    int r1 = t, r2 = t, r3 = t;
    if (tt >= 1 && doc[t - 1] == d0) { c1 = scale[t - 1]; r1 = t - 1; }
    if (tt >= 2 && doc[t - 2] == d0) { c2 = scale[t - 2]; r2 = t - 2; }
    if (tt >= 3 && doc[t - 3] == d0) { c3 = scale[t - 3]; r3 = t - 3; }

    const float* n0 = v + (size_t)t  * DDIM;
    const float* n1 = v + (size_t)r1 * DDIM;
    const float* n2 = v + (size_t)r2 * DDIM;
    const float* n3 = v + (size_t)r3 * DDIM;

    #pragma unroll
    for (int r = 0; r < 2; r++) {
        int d4 = threadIdx.x + r * 256;
        int d  = d4 * 4;
        float4 a0 = *(const float4*)(n0 + d);
        float4 a1 = *(const float4*)(n1 + d);
        float4 a2 = *(const float4*)(n2 + d);
        float4 a3 = *(const float4*)(n3 + d);

        const float* p0 = (const float*)&a0;
        const float* p1 = (const float*)&a1;
        const float* p2 = (const float*)&a2;
        const float* p3 = (const float*)&a3;

        float4 o;
        float* po = (float*)&o;
        #pragma unroll
        for (int i = 0; i < 4; i++) {
            float4 w = *(const float4*)(cw + (size_t)(d + i) * 4); // taps [0..3]
            float res = p0[i] * c0 * w.w + p1[i] * c1 * w.z
                      + p2[i] * c2 * w.y + p3[i] * c3 * w.x;
            po[i] = res / (1.0f + expf(-res));   // SiLU
        }
        *(float4*)(out + (size_t)t * DDIM + d) = o;
    }
}

// ---------------------------------------------------------------------------
extern "C" void kernel_launch(void* const* d_in, const int* in_sizes, int n_in,
                              void* d_out, int out_size) {
    const float* x      = (const float*)d_in[0];
    const int*   doc    = (const int*)  d_in[1];
    const float* W_in   = (const float*)d_in[2];
    const float* W_mix  = (const float*)d_in[3];
    const float* W_k    = (const float*)d_in[4];
    const float* W_v    = (const float*)d_in[5];
    const float* conv_w = (const float*)d_in[6];
    float* out = (float*)d_out;

    __half *xh, *winh, *wkh, *wvh, *wch, *zh, *zm, *yh;
    float *k, *v, *scale;
    cudaGetSymbolAddress((void**)&xh,    g_xh);
    cudaGetSymbolAddress((void**)&winh,  g_winh);
    cudaGetSymbolAddress((void**)&wkh,   g_wkh);
    cudaGetSymbolAddress((void**)&wvh,   g_wvh);
    cudaGetSymbolAddress((void**)&wch,   g_wch);
    cudaGetSymbolAddress((void**)&zh,    g_zh);
    cudaGetSymbolAddress((void**)&zm,    g_zm);
    cudaGetSymbolAddress((void**)&yh,    g_yh);
    cudaGetSymbolAddress((void**)&k,     g_k);
    cudaGetSymbolAddress((void**)&v,     g_v);
    cudaGetSymbolAddress((void**)&scale, g_scale);

    cudaFuncSetAttribute(gemm_f16<true>,
                         cudaFuncAttributeMaxDynamicSharedMemorySize, GEMM_SMEM);
    cudaFuncSetAttribute(gemm_f16<false>,
                         cudaFuncAttributeMaxDynamicSharedMemorySize, GEMM_SMEM);

    // operand conversion to fp16
    half_copy<<<2048, 256>>>(x,    xh,   BT * DDIM / 4);
    half_copy<<<512,  256>>>(W_in, winh, DBDIM * DDIM / 4);
    half_copy<<<512,  256>>>(W_k,  wkh,  DDIM * DBDIM / 4);
    half_copy<<<512,  256>>>(W_v,  wvh,  DDIM * DBDIM / 4);
    combine_wmix<<<(DBDIM * DBDIM + 255) / 256, 256>>>(W_mix, wch);

    // 1) z = xh @ winh^T : [16384,2048] x [512,2048]^T -> fp16
    gemm_f16<true><<<dim3(DBDIM / TBN, BT / TBM, 1), 256, GEMM_SMEM>>>(
        xh, winh, winh, zh, zh, DBDIM, DDIM);

    // 2) zm = zh @ wch^T : [16384,512] x [1536,512]^T -> fp16
    gemm_f16<true><<<dim3(3 * DBDIM / TBN, BT / TBM, 1), 256, GEMM_SMEM>>>(
        zh, wch, wch, zm, zm, 3 * DBDIM, DBDIM);

    // 3) y gather from shifted zm blocks -> fp16
    build_y<<<BT, 128>>>(zm, doc, yh);

    // 4) k = yh @ wkh^T, v = yh @ wvh^T (fused via blockIdx.z) -> fp32
    gemm_f16<false><<<dim3(DDIM / TBN, BT / TBM, 2), 256, GEMM_SMEM>>>(
        yh, wkh, wvh, k, v, DDIM, DBDIM);

    // 5) per-token gate scale
    gate_scale<<<BT, 256>>>(x, k, v, scale);

    // 6) depthwise causal conv + SiLU -> final output
    conv_silu<<<BT, 256>>>(v, scale, doc, conv_w, out);
}